// round 4
// baseline (speedup 1.0000x reference)
#include <cuda_runtime.h>
#include <math.h>

#define W_   512
#define H_   512
#define HW_  (512 * 512)
#define EPS  1e-8f
#define FULLMASK 0xffffffffu

#define NW   4      // warps per CTA
#define BAND 16     // output rows per warp
#define OX   56     // output cols per warp-tile (loads 64: [ox-4, ox+59])

__device__ __forceinline__ float sqrt_approx(float x) {
    float r;
    asm("sqrt.approx.f32 %0, %1;" : "=f"(r) : "f"(x));
    return r;
}

__device__ __forceinline__ float smooth_l1(float a, float b) {
    float d = a - b;
    float ad = fabsf(d);
    return (ad < 1.0f) ? 0.5f * d * d : ad - 0.5f;
}

// One input row, lane owns 2 columns (gx, gx+1).
// Arrays: 0 = sum(P), 1 = sum(P^2), 2 = sum(T), 3 = sum(T^2) over channels.
// Vertical running sums vs[] maintained via a 7-slot per-lane SMEM ring
// (slot S is a compile-time constant -> constant LDS/STS offsets).
// On EMIT rows, horizontal 7-sum via 6 shuffles per array, then std + smoothL1.
template <int S, bool EMIT>
__device__ __forceinline__ void rowstep(
    const float* __restrict__ Pb, const float* __restrict__ Tb,
    bool okx, int oy0, int& i, float2* ringLane,
    float2 (&vs)[4], float& acc, bool o_ok)
{
    const int gy = oy0 - 3 + i;
    const bool ok = okx && (gy >= 0) && (gy < H_);
    const int off = gy << 9;
    const float2 z = make_float2(0.f, 0.f);

    float2 p0 = ok ? *(const float2*)(Pb + off)           : z;
    float2 p1 = ok ? *(const float2*)(Pb + off + HW_)     : z;
    float2 p2 = ok ? *(const float2*)(Pb + off + 2 * HW_) : z;
    float2 t0 = ok ? *(const float2*)(Tb + off)           : z;
    float2 t1 = ok ? *(const float2*)(Tb + off + HW_)     : z;
    float2 t2 = ok ? *(const float2*)(Tb + off + 2 * HW_) : z;

    float2 nv[4];
    nv[0] = make_float2(p0.x + p1.x + p2.x, p0.y + p1.y + p2.y);
    nv[1] = make_float2(fmaf(p0.x, p0.x, fmaf(p1.x, p1.x, p2.x * p2.x)),
                        fmaf(p0.y, p0.y, fmaf(p1.y, p1.y, p2.y * p2.y)));
    nv[2] = make_float2(t0.x + t1.x + t2.x, t0.y + t1.y + t2.y);
    nv[3] = make_float2(fmaf(t0.x, t0.x, fmaf(t1.x, t1.x, t2.x * t2.x)),
                        fmaf(t0.y, t0.y, fmaf(t1.y, t1.y, t2.y * t2.y)));

#pragma unroll
    for (int a = 0; a < 4; a++) {
        float2 ev = ringLane[a * 7 * 32 + S * 32];
        vs[a].x += nv[a].x - ev.x;
        vs[a].y += nv[a].y - ev.y;
        ringLane[a * 7 * 32 + S * 32] = nv[a];
    }

    if (EMIT) {
        float h0[4], h1[4];
#pragma unroll
        for (int a = 0; a < 4; a++) {
            float v0 = vs[a].x, v1 = vs[a].y;
            float sa = __shfl_up_sync  (FULLMASK, v1, 2);   // col gx-3
            float sb = __shfl_up_sync  (FULLMASK, v0, 1);   // col gx-2
            float sc = __shfl_up_sync  (FULLMASK, v1, 1);   // col gx-1
            float sd = __shfl_down_sync(FULLMASK, v0, 1);   // col gx+2
            float se = __shfl_down_sync(FULLMASK, v1, 1);   // col gx+3
            float sf = __shfl_down_sync(FULLMASK, v0, 2);   // col gx+4
            h0[a] = ((sa + sb) + (sc + v0)) + ((v1 + sd) + se);  // center gx
            h1[a] = h0[a] - sa + sf;                             // center gx+1
        }
        const float inv_n = 1.0f / 147.0f;
        float mp0 = h0[0] * inv_n;
        float sp0 = sqrt_approx(fmaf(-mp0, mp0, h0[1] * inv_n) + EPS);
        float mt0 = h0[2] * inv_n;
        float st0 = sqrt_approx(fmaf(-mt0, mt0, h0[3] * inv_n) + EPS);
        float mp1 = h1[0] * inv_n;
        float sp1 = sqrt_approx(fmaf(-mp1, mp1, h1[1] * inv_n) + EPS);
        float mt1 = h1[2] * inv_n;
        float st1 = sqrt_approx(fmaf(-mt1, mt1, h1[3] * inv_n) + EPS);
        float f = smooth_l1(sp0, st0) + smooth_l1(sp1, st1);
        acc += o_ok ? f : 0.f;
    }
    i++;
}

__global__ __launch_bounds__(128, 7)
void dist_loss_kernel(const float* __restrict__ pred,
                      const float* __restrict__ tgt,
                      float* __restrict__ out)
{
    __shared__ float2 ring_s[NW][4][7][32];   // per-lane private ring slots
    __shared__ float  wsum[NW];

    const int L  = threadIdx.x & 31;
    const int w  = threadIdx.x >> 5;
    const int ox = blockIdx.x * OX;
    const int oy0 = (blockIdx.y * NW + w) * BAND;
    const size_t bofs = (size_t)blockIdx.z * 3 * HW_;

    const int gx = ox - 4 + 2 * L;                 // even; lane's 2 columns
    const bool okx = (gx >= 0) && (gx < W_);
    const int gxs = okx ? gx : 0;                  // avoid OOB pointer math
    const float* Pb = pred + bofs + gxs;
    const float* Tb = tgt  + bofs + gxs;

    // output predicate: both of the lane's columns in [ox, ox+55] and < W
    const bool o_ok = (L >= 2) && (L <= 29) && (gx < W_);

    float2* ringLane = &ring_s[w][0][0][L];
#pragma unroll
    for (int a = 0; a < 4; a++)
#pragma unroll
        for (int s = 0; s < 7; s++)
            ringLane[a * 7 * 32 + s * 32] = make_float2(0.f, 0.f);

    float2 vs[4];
#pragma unroll
    for (int a = 0; a < 4; a++) vs[a] = make_float2(0.f, 0.f);

    float acc = 0.f;
    int i = 0;

    // 22 input rows: 6 warm-up + 16 emitting
    rowstep<0, false>(Pb, Tb, okx, oy0, i, ringLane, vs, acc, o_ok);
    rowstep<1, false>(Pb, Tb, okx, oy0, i, ringLane, vs, acc, o_ok);
    rowstep<2, false>(Pb, Tb, okx, oy0, i, ringLane, vs, acc, o_ok);
    rowstep<3, false>(Pb, Tb, okx, oy0, i, ringLane, vs, acc, o_ok);
    rowstep<4, false>(Pb, Tb, okx, oy0, i, ringLane, vs, acc, o_ok);
    rowstep<5, false>(Pb, Tb, okx, oy0, i, ringLane, vs, acc, o_ok);
    rowstep<6, true >(Pb, Tb, okx, oy0, i, ringLane, vs, acc, o_ok);
#pragma unroll 1
    for (int c = 0; c < 2; c++) {
        rowstep<0, true>(Pb, Tb, okx, oy0, i, ringLane, vs, acc, o_ok);
        rowstep<1, true>(Pb, Tb, okx, oy0, i, ringLane, vs, acc, o_ok);
        rowstep<2, true>(Pb, Tb, okx, oy0, i, ringLane, vs, acc, o_ok);
        rowstep<3, true>(Pb, Tb, okx, oy0, i, ringLane, vs, acc, o_ok);
        rowstep<4, true>(Pb, Tb, okx, oy0, i, ringLane, vs, acc, o_ok);
        rowstep<5, true>(Pb, Tb, okx, oy0, i, ringLane, vs, acc, o_ok);
        rowstep<6, true>(Pb, Tb, okx, oy0, i, ringLane, vs, acc, o_ok);
    }
    rowstep<0, true>(Pb, Tb, okx, oy0, i, ringLane, vs, acc, o_ok);

    // warp + block reduce
#pragma unroll
    for (int o = 16; o > 0; o >>= 1)
        acc += __shfl_xor_sync(FULLMASK, acc, o);
    if (L == 0) wsum[w] = acc;
    __syncthreads();
    if (threadIdx.x == 0) {
        float s = wsum[0] + wsum[1] + wsum[2] + wsum[3];
        atomicAdd(out, s * (1.0f / (16.0f * 512.0f * 512.0f)));
    }
}

extern "C" void kernel_launch(void* const* d_in, const int* in_sizes, int n_in,
                              void* d_out, int out_size)
{
    const float* pred = (const float*)d_in[0];
    const float* tgt  = (const float*)d_in[1];
    float* out = (float*)d_out;

    cudaMemsetAsync(out, 0, sizeof(float));

    dim3 block(128, 1, 1);
    // x: ceil(512/56)=10 tiles, y: 512/(16*4)=8, z: batch 16  -> 1280 CTAs
    dim3 grid((W_ + OX - 1) / OX, H_ / (BAND * NW), 16);
    dist_loss_kernel<<<grid, block>>>(pred, tgt, out);
}